// round 1
// baseline (speedup 1.0000x reference)
#include <cuda_runtime.h>
#include <cstdint>

#define NB   128   // batch
#define NS   12    // S
#define NL   128   // L
#define NE   512   // E
#define NE2  1024  // 2E
#define NH   512   // H
#define NH3  1536  // 3H
#define NKIN 2304  // E2 + 2V + P

// ---------------- scratch (static device globals: no allocations) ----------------
__device__ int   g_idx[NB];
__device__ int   g_gc[NB];
__device__ float g_mask_sum;
__device__ float g_inps[NB * NS * NE2];     // 6.3 MB
__device__ float g_h[NB * NH];              // GRU hidden state
__device__ float g_xproj[NB * NS * NH3];    // 9.4 MB
__device__ float g_gh[NB * NH3];
__device__ float g_outh[NB * NS * NH];      // GRU outputs
__device__ float g_hpart[NB * NS * NE];
__device__ float g_epart[NB * NL * NE];     // 33.5 MB
__device__ float g_plan_partial[2048];

// ---------------- math helpers ----------------
__device__ __forceinline__ float fast_tanh(float x) {
    float y;
    asm("tanh.approx.f32 %0, %1;" : "=f"(y) : "f"(x));
    return y;
}
__device__ __forceinline__ float sigmoidf(float x) {
    return 1.f / (1.f + __expf(-x));
}
__device__ __forceinline__ float softplusf(float x) {
    // log1p(exp(x)), stable. For x>15, log1p(exp(x)) == x to fp32 precision.
    return (x > 15.f) ? x : log1pf(__expf(x));
}

// ---------------- kernel 1: stable descending sort of group_count ----------------
__global__ void k_sort(const int* __restrict__ gc) {
    __shared__ int s_gc[NB];
    __shared__ int red[NB];
    int t = threadIdx.x;  // 128 threads
    s_gc[t] = gc[t];
    __syncthreads();
    int my = s_gc[t];
    int rank = 0;
    #pragma unroll 8
    for (int j = 0; j < NB; j++) {
        int v = s_gc[j];
        rank += (v > my) || (v == my && j < t);  // stable: argsort(-gc)
    }
    g_idx[rank] = t;
    g_gc[rank]  = my;
    red[t] = my;
    __syncthreads();
    for (int off = 64; off > 0; off >>= 1) {
        if (t < off) red[t] += red[t + off];
        __syncthreads();
    }
    if (t == 0) g_mask_sum = (float)red[0];
}

// ---------------- kernel 2: alpha + inps = einsum('bsl,ble->bse') ----------------
__global__ void k_inps(const float* __restrict__ enc, const int* __restrict__ segments) {
    __shared__ float s_a[NS][NL];   // alpha
    __shared__ float s_inv[NS];
    int b = blockIdx.x, t = threadIdx.x;  // 256 threads
    int p = g_idx[b];                     // sorted segments index; enc stays at b
    for (int i = t; i < NS * NL; i += 256) {
        int s = i >> 7, l = i & 127;
        float v = 0.f;
        if (s > 0) v = (float)segments[(p * NS + (s - 1)) * NL + l];
        s_a[s][l] = v;
    }
    __syncthreads();
    if (t < NS) {
        float sum = 0.f;
        for (int l = 0; l < NL; l++) sum += s_a[t][l];
        s_inv[t] = 1.f / (sum + 1.f);
    }
    __syncthreads();
    for (int i = t; i < NS * NL; i += 256) {
        int s = i >> 7;
        s_a[s][i & 127] *= s_inv[s];
    }
    __syncthreads();
    const float* encb = enc + (size_t)b * NL * NE2;
    #pragma unroll
    for (int eo = 0; eo < NE2 / 256; eo++) {
        int e = eo * 256 + t;
        float acc[NS];
        #pragma unroll
        for (int s = 0; s < NS; s++) acc[s] = 0.f;
        for (int l = 0; l < NL; l++) {
            float v = encb[l * NE2 + e];
            #pragma unroll
            for (int s = 0; s < NS; s++) acc[s] += s_a[s][l] * v;
        }
        #pragma unroll
        for (int s = 0; s < NS; s++) g_inps[(b * NS + s) * NE2 + e] = acc[s];
    }
}

// ---------------- generic tiled SGEMM: C[m,n] = sum_k A[m,k]*W[n,k] + bias[n] ----------------
template <int BM, int BN, int BK, int TM, int TN, int NTHR>
__global__ void sgemm_nt(const float* __restrict__ A, int lda,
                         const float* __restrict__ W, int ldw,
                         const float* __restrict__ bias,
                         float* __restrict__ C, int ldc,
                         int M, int N, int K) {
    __shared__ float As[BK][BM + 4];
    __shared__ float Ws[BK][BN + 4];
    const int tid = threadIdx.x;
    const int tn  = tid % (BN / TN);
    const int tm  = tid / (BN / TN);
    const int m0  = blockIdx.y * BM;
    const int n0  = blockIdx.x * BN;

    float acc[TM][TN];
    #pragma unroll
    for (int i = 0; i < TM; i++)
        #pragma unroll
        for (int j = 0; j < TN; j++) acc[i][j] = 0.f;

    for (int k0 = 0; k0 < K; k0 += BK) {
        #pragma unroll
        for (int i = tid; i < BM * BK; i += NTHR) {
            int m = i / BK, k = i % BK;
            int gm = m0 + m;
            As[k][m] = (gm < M) ? A[(size_t)gm * lda + k0 + k] : 0.f;
        }
        #pragma unroll
        for (int i = tid; i < BN * BK; i += NTHR) {
            int n = i / BK, k = i % BK;
            int gn = n0 + n;
            Ws[k][n] = (gn < N) ? W[(size_t)gn * ldw + k0 + k] : 0.f;
        }
        __syncthreads();
        #pragma unroll 4
        for (int k = 0; k < BK; k++) {
            float ra[TM], rb[TN];
            #pragma unroll
            for (int i = 0; i < TM; i++) ra[i] = As[k][tm * TM + i];
            #pragma unroll
            for (int j = 0; j < TN; j++) rb[j] = Ws[k][tn * TN + j];
            #pragma unroll
            for (int i = 0; i < TM; i++)
                #pragma unroll
                for (int j = 0; j < TN; j++) acc[i][j] += ra[i] * rb[j];
        }
        __syncthreads();
    }
    #pragma unroll
    for (int i = 0; i < TM; i++) {
        int gm = m0 + tm * TM + i;
        if (gm >= M) continue;
        #pragma unroll
        for (int j = 0; j < TN; j++) {
            int gn = n0 + tn * TN + j;
            if (gn < N) {
                float v = acc[i][j];
                if (bias) v += bias[gn];
                C[(size_t)gm * ldc + gn] = v;
            }
        }
    }
}

// ---------------- GRU gate update (one step) ----------------
__global__ void k_gru(int s) {
    int i = blockIdx.x * 256 + threadIdx.x;  // B*H threads
    int b = i / NH, h = i % NH;
    const float* x  = g_xproj + (size_t)(b * NS + s) * NH3;
    const float* gh = g_gh + (size_t)b * NH3;
    float r  = sigmoidf(x[h] + gh[h]);
    float z  = sigmoidf(x[NH + h] + gh[NH + h]);
    float n  = tanhf(x[2 * NH + h] + r * gh[2 * NH + h]);
    float hp = g_h[i];
    float hn = (1.f - z) * n + z * hp;
    g_h[i] = hn;
    g_outh[(size_t)(b * NS + s) * NH + h] = hn;
}

// ---------------- fused plan logits + BCE (never materializes tanh tensor) ----------------
__global__ void k_plan(const int* __restrict__ segments,
                       const float* __restrict__ W_p2,
                       const float* __restrict__ b_p2) {
    __shared__ float s_h[NS][NE];   // hpart rows for this b (24 KB)
    __shared__ float s_w2[NE];
    __shared__ float s_warp[8];
    int t = threadIdx.x;                 // 256
    int b = blockIdx.y, ltile = blockIdx.x;  // grid (16, B)
    for (int i = t; i < NS * NE; i += 256) s_h[i >> 9][i & 511] = g_hpart[(size_t)b * NS * NE + i];
    for (int i = t; i < NE; i += 256) s_w2[i] = W_p2[i];
    __syncthreads();

    int warp = t >> 5, lane = t & 31;
    int l = ltile * 8 + warp;
    const float* ep = g_epart + (size_t)(b * NL + l) * NE;
    float epr[16];
    #pragma unroll
    for (int j = 0; j < 16; j++) epr[j] = ep[lane + 32 * j];

    int gcb = g_gc[b];
    int p   = g_idx[b];
    float bp2 = b_p2[0];
    float local = 0.f;
    for (int s = 0; s < gcb; s++) {   // mask: s < gc[b]
        float acc = 0.f;
        #pragma unroll
        for (int j = 0; j < 16; j++) {
            int e = lane + 32 * j;
            acc += fast_tanh(s_h[s][e] + epr[j]) * s_w2[e];
        }
        #pragma unroll
        for (int off = 16; off; off >>= 1) acc += __shfl_xor_sync(0xffffffffu, acc, off);
        if (lane == 0) {
            float pl  = acc + bp2;
            float tgt = (float)segments[(p * NS + s) * NL + l];
            local += softplusf(pl) - pl * tgt;
        }
    }
    if (lane == 0) s_warp[warp] = local;
    __syncthreads();
    if (t == 0) {
        float sum = 0.f;
        #pragma unroll
        for (int w = 0; w < 8; w++) sum += s_warp[w];
        g_plan_partial[b * 16 + ltile] = sum;
    }
}

// ---------------- stop loss + final deterministic reduction ----------------
__global__ void k_final(const float* __restrict__ W_stop,
                        const float* __restrict__ b_stop,
                        float* __restrict__ out) {
    __shared__ float s_w[NH];
    __shared__ float s_stop[32];
    __shared__ float s_red[1024];
    int t = threadIdx.x;  // 1024
    for (int i = t; i < NH; i += 1024) s_w[i] = W_stop[i];
    __syncthreads();

    int warp = t >> 5, lane = t & 31;
    float stop_local = 0.f;
    for (int bs = warp; bs < NB * NS; bs += 32) {
        const float* o = g_outh + (size_t)bs * NH;
        float a = 0.f;
        #pragma unroll
        for (int j = 0; j < 16; j++) a += o[lane + 32 * j] * s_w[lane + 32 * j];
        #pragma unroll
        for (int off = 16; off; off >>= 1) a += __shfl_xor_sync(0xffffffffu, a, off);
        if (lane == 0) {
            int b = bs / NS, s = bs % NS;
            int gcb = g_gc[b];
            if (s < gcb) {
                float logit = a + b_stop[0];
                float label = (s == gcb - 1) ? 1.f : 0.f;
                stop_local += softplusf(logit) - logit * label;
            }
        }
    }
    if (lane == 0) s_stop[warp] = stop_local;

    s_red[t] = g_plan_partial[t] + g_plan_partial[t + 1024];
    __syncthreads();
    for (int off = 512; off; off >>= 1) {
        if (t < off) s_red[t] += s_red[t + off];
        __syncthreads();
    }
    if (t == 0) {
        float stop_sum = 0.f;
        #pragma unroll
        for (int w = 0; w < 32; w++) stop_sum += s_stop[w];
        float ms = g_mask_sum;
        out[0] = stop_sum / ms;                 // stop_loss
        out[1] = s_red[0] / (ms * (float)NL);   // group_loss
    }
}

// ---------------- launch ----------------
extern "C" void kernel_launch(void* const* d_in, const int* in_sizes, int n_in,
                              void* d_out, int out_size) {
    const float* enc    = (const float*)d_in[0];
    const int*   segs   = (const int*)d_in[1];
    const int*   gcnt   = (const int*)d_in[2];
    const float* ginit  = (const float*)d_in[3];
    const float* W_init = (const float*)d_in[4];
    const float* b_init = (const float*)d_in[5];
    const float* W_ih   = (const float*)d_in[6];
    const float* b_ih   = (const float*)d_in[7];
    const float* W_hh   = (const float*)d_in[8];
    const float* b_hh   = (const float*)d_in[9];
    const float* W_p1   = (const float*)d_in[10];
    const float* b_p1   = (const float*)d_in[11];
    const float* W_p2   = (const float*)d_in[12];
    const float* b_p2   = (const float*)d_in[13];
    const float* W_stop = (const float*)d_in[14];
    const float* b_stop = (const float*)d_in[15];
    float* out = (float*)d_out;

    float *p_inps, *p_h, *p_xproj, *p_gh, *p_outh, *p_hpart, *p_epart;
    cudaGetSymbolAddress((void**)&p_inps,  g_inps);
    cudaGetSymbolAddress((void**)&p_h,     g_h);
    cudaGetSymbolAddress((void**)&p_xproj, g_xproj);
    cudaGetSymbolAddress((void**)&p_gh,    g_gh);
    cudaGetSymbolAddress((void**)&p_outh,  g_outh);
    cudaGetSymbolAddress((void**)&p_hpart, g_hpart);
    cudaGetSymbolAddress((void**)&p_epart, g_epart);

    k_sort<<<1, NB>>>(gcnt);
    k_inps<<<NB, 256>>>(enc, segs);

    // h0 = ginit @ W_init.T + b_init    (128 x 512, K=2304)
    sgemm_nt<16, 64, 16, 2, 4, 128><<<dim3(NH / 64, NB / 16), 128>>>(
        ginit, NKIN, W_init, NKIN, b_init, p_h, NH, NB, NH, NKIN);

    // x_proj = inps @ W_ih.T + b_ih     (1536 x 1536, K=1024)
    sgemm_nt<128, 128, 16, 8, 8, 256><<<dim3(NH3 / 128, (NB * NS) / 128), 256>>>(
        p_inps, NE2, W_ih, NE2, b_ih, p_xproj, NH3, NB * NS, NH3, NE2);

    // GRU scan
    for (int s = 0; s < NS; s++) {
        sgemm_nt<32, 64, 16, 4, 4, 128><<<dim3(NH3 / 64, NB / 32), 128>>>(
            p_h, NH, W_hh, NH, b_hh, p_gh, NH3, NB, NH3, NH);
        k_gru<<<(NB * NH) / 256, 256>>>(s);
    }

    // hpart = outputs @ W1h.T           (1536 x 512, K=512), W1h = W_p1[:, :512]
    sgemm_nt<64, 64, 16, 4, 4, 256><<<dim3(NE / 64, (NB * NS) / 64), 256>>>(
        p_outh, NH, W_p1, NH3, nullptr, p_hpart, NE, NB * NS, NE, NH);

    // epart = enc @ W1e.T + b_p1        (16384 x 512, K=1024), W1e = W_p1[:, 512:]
    sgemm_nt<128, 128, 16, 8, 8, 256><<<dim3(NE / 128, (NB * NL) / 128), 256>>>(
        enc, NE2, W_p1 + NH, NH3, b_p1, p_epart, NE, NB * NL, NE, NE2);

    // fused plan logits + group BCE partials
    k_plan<<<dim3(16, NB), 256>>>(segs, W_p2, b_p2);

    // stop loss + final reduction -> out[0]=stop_loss, out[1]=group_loss
    k_final<<<1, 1024>>>(W_stop, b_stop, out);
}

// round 2
// speedup vs baseline: 3.4308x; 3.4308x over previous
#include <cuda_runtime.h>
#include <cuda_bf16.h>
#include <mma.h>
#include <cstdint>

using namespace nvcuda;

#define NB   128   // batch
#define NS   12    // S
#define NL   128   // L
#define NE   512   // E
#define NE2  1024  // 2E
#define NH   512   // H
#define NH3  1536  // 3H
#define NKIN 2304  // E2 + 2V + P

// ---------------- scratch (static device globals: no allocations) ----------------
__device__ int   g_idx[NB];
__device__ int   g_gc[NB];
__device__ float g_mask_sum;
__device__ float g_inps[NB * NS * NE2];
__device__ float g_h[NB * NH];
__device__ float g_xproj[NB * NS * NH3];
__device__ float g_gh[NB * NH3];
__device__ float g_outh[NB * NS * NH];
__device__ float g_hpart[NB * NS * NE];
__device__ float g_epart[NB * NL * NE];
__device__ float g_plan_partial[2048];

// ---------------- math helpers ----------------
__device__ __forceinline__ float fast_tanh(float x) {
    float y;
    asm("tanh.approx.f32 %0, %1;" : "=f"(y) : "f"(x));
    return y;
}
__device__ __forceinline__ float sigmoidf(float x) {
    return 1.f / (1.f + __expf(-x));
}
__device__ __forceinline__ float softplusf(float x) {
    return (x > 15.f) ? x : log1pf(__expf(x));
}

// ---------------- kernel 1: stable descending sort of group_count ----------------
__global__ void k_sort(const int* __restrict__ gc) {
    __shared__ int s_gc[NB];
    __shared__ int red[NB];
    int t = threadIdx.x;  // 128 threads
    s_gc[t] = gc[t];
    __syncthreads();
    int my = s_gc[t];
    int rank = 0;
    #pragma unroll 8
    for (int j = 0; j < NB; j++) {
        int v = s_gc[j];
        rank += (v > my) || (v == my && j < t);  // stable argsort(-gc)
    }
    g_idx[rank] = t;
    g_gc[rank]  = my;
    red[t] = my;
    __syncthreads();
    for (int off = 64; off > 0; off >>= 1) {
        if (t < off) red[t] += red[t + off];
        __syncthreads();
    }
    if (t == 0) g_mask_sum = (float)red[0];
}

// ---------------- kernel 2: alpha + inps = einsum('bsl,ble->bse') ----------------
__global__ void k_inps(const float* __restrict__ enc, const int* __restrict__ segments) {
    __shared__ float s_a[NS][NL];
    __shared__ float s_inv[NS];
    int b = blockIdx.x, t = threadIdx.x;  // 256 threads
    int p = g_idx[b];
    for (int i = t; i < NS * NL; i += 256) {
        int s = i >> 7, l = i & 127;
        float v = 0.f;
        if (s > 0) v = (float)segments[(p * NS + (s - 1)) * NL + l];
        s_a[s][l] = v;
    }
    __syncthreads();
    if (t < NS) {
        float sum = 0.f;
        for (int l = 0; l < NL; l++) sum += s_a[t][l];
        s_inv[t] = 1.f / (sum + 1.f);
    }
    __syncthreads();
    for (int i = t; i < NS * NL; i += 256) {
        int s = i >> 7;
        s_a[s][i & 127] *= s_inv[s];
    }
    __syncthreads();
    const float* encb = enc + (size_t)b * NL * NE2;
    #pragma unroll
    for (int eo = 0; eo < NE2 / 256; eo++) {
        int e = eo * 256 + t;
        float acc[NS];
        #pragma unroll
        for (int s = 0; s < NS; s++) acc[s] = 0.f;
        for (int l = 0; l < NL; l++) {
            float v = encb[l * NE2 + e];
            #pragma unroll
            for (int s = 0; s < NS; s++) acc[s] += s_a[s][l] * v;
        }
        #pragma unroll
        for (int s = 0; s < NS; s++) g_inps[(b * NS + s) * NE2 + e] = acc[s];
    }
}

// ---------------- bf16 WMMA GEMM: C[m,n] = sum_k A[m,k] * W[n,k] (no bias) ----------------
// BM=128, BN=128, BK=32, 256 threads = 8 warps, warp tile 64x32 (warp grid 2m x 4n).
// Requires: M % 128 == 0 (or M == BM via gridDim.y), N % 128 == 0 or N%32... we only call
// with M,N multiples of tile coverage and K % 32 == 0, lda/ldw % 4 == 0.
__global__ __launch_bounds__(256) void gemm_wmma(
    const float* __restrict__ A, int lda,
    const float* __restrict__ W, int ldw,
    float* __restrict__ C, int ldc, int K) {
    constexpr int BK = 32;
    constexpr int LDS = BK + 8;  // 40 halves (80 B) stride: aligned, low-conflict
    __shared__ __align__(32) __nv_bfloat16 As[128][LDS];
    __shared__ __align__(32) __nv_bfloat16 Ws[128][LDS];

    const int tid  = threadIdx.x;
    const int warp = tid >> 5;
    const int wm   = warp & 1;        // 0..1  -> m offset wm*64
    const int wn   = warp >> 1;       // 0..3  -> n offset wn*32
    const int m0   = blockIdx.y * 128;
    const int n0   = blockIdx.x * 128;

    wmma::fragment<wmma::accumulator, 16, 16, 16, float> acc[4][2];
    #pragma unroll
    for (int i = 0; i < 4; i++)
        #pragma unroll
        for (int j = 0; j < 2; j++) wmma::fill_fragment(acc[i][j], 0.f);

    for (int k0 = 0; k0 < K; k0 += BK) {
        // cooperative load + fp32->bf16 convert; 128x32 each for A and W
        #pragma unroll
        for (int it = 0; it < 4; it++) {
            int i = it * 256 + tid;          // 0..1023
            int r = i >> 3, c = (i & 7) * 4; // row, col(4-wide)
            float4 va = *reinterpret_cast<const float4*>(A + (size_t)(m0 + r) * lda + k0 + c);
            __nv_bfloat162 a0 = {__float2bfloat16(va.x), __float2bfloat16(va.y)};
            __nv_bfloat162 a1 = {__float2bfloat16(va.z), __float2bfloat16(va.w)};
            *reinterpret_cast<__nv_bfloat162*>(&As[r][c])     = a0;
            *reinterpret_cast<__nv_bfloat162*>(&As[r][c + 2]) = a1;
            float4 vw = *reinterpret_cast<const float4*>(W + (size_t)(n0 + r) * ldw + k0 + c);
            __nv_bfloat162 w0 = {__float2bfloat16(vw.x), __float2bfloat16(vw.y)};
            __nv_bfloat162 w1 = {__float2bfloat16(vw.z), __float2bfloat16(vw.w)};
            *reinterpret_cast<__nv_bfloat162*>(&Ws[r][c])     = w0;
            *reinterpret_cast<__nv_bfloat162*>(&Ws[r][c + 2]) = w1;
        }
        __syncthreads();
        #pragma unroll
        for (int kk = 0; kk < BK; kk += 16) {
            wmma::fragment<wmma::matrix_a, 16, 16, 16, __nv_bfloat16, wmma::row_major> af[4];
            wmma::fragment<wmma::matrix_b, 16, 16, 16, __nv_bfloat16, wmma::col_major> bf[2];
            #pragma unroll
            for (int i = 0; i < 4; i++)
                wmma::load_matrix_sync(af[i], &As[wm * 64 + i * 16][kk], LDS);
            #pragma unroll
            for (int j = 0; j < 2; j++)
                wmma::load_matrix_sync(bf[j], &Ws[wn * 32 + j * 16][kk], LDS);
            #pragma unroll
            for (int i = 0; i < 4; i++)
                #pragma unroll
                for (int j = 0; j < 2; j++)
                    wmma::mma_sync(acc[i][j], af[i], bf[j], acc[i][j]);
        }
        __syncthreads();
    }
    #pragma unroll
    for (int i = 0; i < 4; i++)
        #pragma unroll
        for (int j = 0; j < 2; j++)
            wmma::store_matrix_sync(
                C + (size_t)(m0 + wm * 64 + i * 16) * ldc + n0 + wn * 32 + j * 16,
                acc[i][j], ldc, wmma::mem_row_major);
}

// ---------------- h0 bias add ----------------
__global__ void k_bias_h0(const float* __restrict__ b_init) {
    int i = blockIdx.x * 256 + threadIdx.x;  // NB*NH
    g_h[i] += b_init[i & (NH - 1)];
}

// ---------------- GRU gate update (biases folded in here) ----------------
__global__ void k_gru(int s, const float* __restrict__ b_ih, const float* __restrict__ b_hh) {
    int i = blockIdx.x * 256 + threadIdx.x;  // B*H threads
    int b = i / NH, h = i % NH;
    const float* x  = g_xproj + (size_t)(b * NS + s) * NH3;
    const float* gh = g_gh + (size_t)b * NH3;
    float r  = sigmoidf(x[h]          + b_ih[h]          + gh[h]          + b_hh[h]);
    float z  = sigmoidf(x[NH + h]     + b_ih[NH + h]     + gh[NH + h]     + b_hh[NH + h]);
    float n  = tanhf(x[2 * NH + h] + b_ih[2 * NH + h] + r * (gh[2 * NH + h] + b_hh[2 * NH + h]));
    float hp = g_h[i];
    float hn = (1.f - z) * n + z * hp;
    g_h[i] = hn;
    g_outh[(size_t)(b * NS + s) * NH + h] = hn;
}

// ---------------- fused plan logits + BCE (adds b_p1 to epart here) ----------------
__global__ void k_plan(const int* __restrict__ segments,
                       const float* __restrict__ b_p1,
                       const float* __restrict__ W_p2,
                       const float* __restrict__ b_p2) {
    __shared__ float s_h[NS][NE];
    __shared__ float s_w2[NE];
    __shared__ float s_b1[NE];
    __shared__ float s_warp[8];
    int t = threadIdx.x;                     // 256
    int b = blockIdx.y, ltile = blockIdx.x;  // grid (16, B)
    for (int i = t; i < NS * NE; i += 256) s_h[i >> 9][i & 511] = g_hpart[(size_t)b * NS * NE + i];
    for (int i = t; i < NE; i += 256) { s_w2[i] = W_p2[i]; s_b1[i] = b_p1[i]; }
    __syncthreads();

    int warp = t >> 5, lane = t & 31;
    int l = ltile * 8 + warp;
    const float* ep = g_epart + (size_t)(b * NL + l) * NE;
    float epr[16];
    #pragma unroll
    for (int j = 0; j < 16; j++) {
        int e = lane + 32 * j;
        epr[j] = ep[e] + s_b1[e];
    }

    int gcb = g_gc[b];
    int p   = g_idx[b];
    float bp2 = b_p2[0];
    float local = 0.f;
    for (int s = 0; s < gcb; s++) {
        float acc = 0.f;
        #pragma unroll
        for (int j = 0; j < 16; j++) {
            int e = lane + 32 * j;
            acc += fast_tanh(s_h[s][e] + epr[j]) * s_w2[e];
        }
        #pragma unroll
        for (int off = 16; off; off >>= 1) acc += __shfl_xor_sync(0xffffffffu, acc, off);
        if (lane == 0) {
            float pl  = acc + bp2;
            float tgt = (float)segments[(p * NS + s) * NL + l];
            local += softplusf(pl) - pl * tgt;
        }
    }
    if (lane == 0) s_warp[warp] = local;
    __syncthreads();
    if (t == 0) {
        float sum = 0.f;
        #pragma unroll
        for (int w = 0; w < 8; w++) sum += s_warp[w];
        g_plan_partial[b * 16 + ltile] = sum;
    }
}

// ---------------- stop loss + final deterministic reduction ----------------
__global__ void k_final(const float* __restrict__ W_stop,
                        const float* __restrict__ b_stop,
                        float* __restrict__ out) {
    __shared__ float s_w[NH];
    __shared__ float s_stop[32];
    __shared__ float s_red[1024];
    int t = threadIdx.x;  // 1024
    for (int i = t; i < NH; i += 1024) s_w[i] = W_stop[i];
    __syncthreads();

    int warp = t >> 5, lane = t & 31;
    float stop_local = 0.f;
    for (int bs = warp; bs < NB * NS; bs += 32) {
        const float* o = g_outh + (size_t)bs * NH;
        float a = 0.f;
        #pragma unroll
        for (int j = 0; j < 16; j++) a += o[lane + 32 * j] * s_w[lane + 32 * j];
        #pragma unroll
        for (int off = 16; off; off >>= 1) a += __shfl_xor_sync(0xffffffffu, a, off);
        if (lane == 0) {
            int b = bs / NS, s = bs % NS;
            int gcb = g_gc[b];
            if (s < gcb) {
                float logit = a + b_stop[0];
                float label = (s == gcb - 1) ? 1.f : 0.f;
                stop_local += softplusf(logit) - logit * label;
            }
        }
    }
    if (lane == 0) s_stop[warp] = stop_local;

    s_red[t] = g_plan_partial[t] + g_plan_partial[t + 1024];
    __syncthreads();
    for (int off = 512; off; off >>= 1) {
        if (t < off) s_red[t] += s_red[t + off];
        __syncthreads();
    }
    if (t == 0) {
        float stop_sum = 0.f;
        #pragma unroll
        for (int w = 0; w < 32; w++) stop_sum += s_stop[w];
        float ms = g_mask_sum;
        out[0] = stop_sum / ms;                 // stop_loss
        out[1] = s_red[0] / (ms * (float)NL);   // group_loss
    }
}

// ---------------- launch ----------------
extern "C" void kernel_launch(void* const* d_in, const int* in_sizes, int n_in,
                              void* d_out, int out_size) {
    const float* enc    = (const float*)d_in[0];
    const int*   segs   = (const int*)d_in[1];
    const int*   gcnt   = (const int*)d_in[2];
    const float* ginit  = (const float*)d_in[3];
    const float* W_init = (const float*)d_in[4];
    const float* b_init = (const float*)d_in[5];
    const float* W_ih   = (const float*)d_in[6];
    const float* b_ih   = (const float*)d_in[7];
    const float* W_hh   = (const float*)d_in[8];
    const float* b_hh   = (const float*)d_in[9];
    const float* W_p1   = (const float*)d_in[10];
    const float* b_p1   = (const float*)d_in[11];
    const float* W_p2   = (const float*)d_in[12];
    const float* b_p2   = (const float*)d_in[13];
    const float* W_stop = (const float*)d_in[14];
    const float* b_stop = (const float*)d_in[15];
    float* out = (float*)d_out;

    float *p_inps, *p_h, *p_xproj, *p_gh, *p_outh, *p_hpart, *p_epart;
    cudaGetSymbolAddress((void**)&p_inps,  g_inps);
    cudaGetSymbolAddress((void**)&p_h,     g_h);
    cudaGetSymbolAddress((void**)&p_xproj, g_xproj);
    cudaGetSymbolAddress((void**)&p_gh,    g_gh);
    cudaGetSymbolAddress((void**)&p_outh,  g_outh);
    cudaGetSymbolAddress((void**)&p_hpart, g_hpart);
    cudaGetSymbolAddress((void**)&p_epart, g_epart);

    k_sort<<<1, NB>>>(gcnt);
    k_inps<<<NB, 256>>>(enc, segs);

    // h0 = ginit @ W_init.T  (128 x 512, K=2304), bias added after
    gemm_wmma<<<dim3(NH / 128, NB / 128), 256>>>(ginit, NKIN, W_init, NKIN, p_h, NH, NKIN);
    k_bias_h0<<<(NB * NH) / 256, 256>>>(b_init);

    // x_proj = inps @ W_ih.T  (1536 x 1536, K=1024); b_ih folded into k_gru
    gemm_wmma<<<dim3(NH3 / 128, (NB * NS) / 128), 256>>>(p_inps, NE2, W_ih, NE2, p_xproj, NH3, NE2);

    // GRU scan: gh = h @ W_hh.T (128 x 1536, K=512); b_hh folded into k_gru
    for (int s = 0; s < NS; s++) {
        gemm_wmma<<<dim3(NH3 / 128, NB / 128), 256>>>(p_h, NH, W_hh, NH, p_gh, NH3, NH);
        k_gru<<<(NB * NH) / 256, 256>>>(s, b_ih, b_hh);
    }

    // hpart = outputs @ W1h.T  (1536 x 512, K=512), W1h = W_p1[:, :512]
    gemm_wmma<<<dim3(NE / 128, (NB * NS) / 128), 256>>>(p_outh, NH, W_p1, NH3, p_hpart, NE, NH);

    // epart = enc @ W1e.T  (16384 x 512, K=1024), W1e = W_p1[:, 512:]; b_p1 folded into k_plan
    gemm_wmma<<<dim3(NE / 128, (NB * NL) / 128), 256>>>(enc, NE2, W_p1 + NH, NH3, p_epart, NE, NE2);

    // fused plan logits + group BCE partials
    k_plan<<<dim3(16, NB), 256>>>(segs, b_p1, W_p2, b_p2);

    // stop loss + final reduction -> out[0]=stop_loss, out[1]=group_loss
    k_final<<<1, 1024>>>(W_stop, b_stop, out);
}

// round 3
// speedup vs baseline: 5.9009x; 1.7200x over previous
#include <cuda_runtime.h>
#include <cuda_bf16.h>
#include <mma.h>
#include <cstdint>

using namespace nvcuda;

#define NB   128
#define NS   12
#define NL   128
#define NE   512
#define NE2  1024
#define NH   512
#define NH3  1536
#define NKIN 2304
#define GNC  64    // persistent GRU grid size

// ---------------- scratch ----------------
__device__ int   g_idx[NB];
__device__ int   g_gc[NB];
__device__ float g_mask_sum;
__device__ float g_h[NB * NH];
__device__ float g_xproj[NB * NS * NH3];
__device__ float g_outh[NB * NS * NH];
__device__ float g_hpart[NB * NS * NE];
__device__ float g_epart[NB * NL * NE];
__device__ float g_plan_partial[2048];
__device__ unsigned g_bar_arrive;
__device__ unsigned g_bar_gen;
// bf16 copies
__device__ __nv_bfloat16 g_enc_bf[NB * NL * NE2];
__device__ __nv_bfloat16 g_inps_bf[NB * NS * NE2];
__device__ __nv_bfloat16 g_outh_bf[NB * NS * NH];
__device__ __nv_bfloat16 g_hb[NB * NH];
__device__ __nv_bfloat16 g_wp1_bf[NE * NH3];
__device__ __nv_bfloat16 g_wih_bf[NH3 * NE2];
__device__ __nv_bfloat16 g_ginit_bf[NB * NKIN];
__device__ __nv_bfloat16 g_winit_bf[NH * NKIN];

// ---------------- helpers ----------------
__device__ __forceinline__ float fast_tanh(float x) {
    float y; asm("tanh.approx.f32 %0, %1;" : "=f"(y) : "f"(x)); return y;
}
__device__ __forceinline__ float sigmoidf(float x) { return 1.f / (1.f + __expf(-x)); }
__device__ __forceinline__ float softplusf(float x) { return (x > 15.f) ? x : log1pf(__expf(x)); }

__device__ __forceinline__ void cp16(void* sdst, const void* gsrc) {
    uint32_t s = (uint32_t)__cvta_generic_to_shared(sdst);
    asm volatile("cp.async.cg.shared.global [%0], [%1], 16;\n" :: "r"(s), "l"(gsrc));
}
#define CP_COMMIT() asm volatile("cp.async.commit_group;\n")
#define CP_WAIT1()  asm volatile("cp.async.wait_group 1;\n")
#define CP_WAIT0()  asm volatile("cp.async.wait_group 0;\n")

// ---------------- fp32 -> bf16 convert ----------------
__global__ void k_cvt(const float4* __restrict__ src, __nv_bfloat162* __restrict__ dst, int n4) {
    int i = blockIdx.x * 256 + threadIdx.x;
    if (i < n4) {
        float4 v = src[i];
        dst[2 * i]     = __nv_bfloat162{__float2bfloat16(v.x), __float2bfloat16(v.y)};
        dst[2 * i + 1] = __nv_bfloat162{__float2bfloat16(v.z), __float2bfloat16(v.w)};
    }
}

// ---------------- stable descending sort of group_count ----------------
__global__ void k_sort(const int* __restrict__ gc) {
    __shared__ int s_gc[NB];
    __shared__ int red[NB];
    int t = threadIdx.x;
    s_gc[t] = gc[t];
    __syncthreads();
    int my = s_gc[t];
    int rank = 0;
    #pragma unroll 8
    for (int j = 0; j < NB; j++) {
        int v = s_gc[j];
        rank += (v > my) || (v == my && j < t);
    }
    g_idx[rank] = t;
    g_gc[rank]  = my;
    red[t] = my;
    __syncthreads();
    for (int off = 64; off > 0; off >>= 1) {
        if (t < off) red[t] += red[t + off];
        __syncthreads();
    }
    if (t == 0) g_mask_sum = (float)red[0];
}

// ---------------- alpha + inps einsum; also emits bf16 inps and bf16 enc ----------------
__global__ void k_inps(const float* __restrict__ enc, const int* __restrict__ segments) {
    __shared__ float s_a[NS][NL];
    __shared__ float s_inv[NS];
    int b = blockIdx.x, t = threadIdx.x;  // 256
    int p = g_idx[b];
    for (int i = t; i < NS * NL; i += 256) {
        int s = i >> 7, l = i & 127;
        float v = 0.f;
        if (s > 0) v = (float)segments[(p * NS + (s - 1)) * NL + l];
        s_a[s][l] = v;
    }
    __syncthreads();
    if (t < NS) {
        float sum = 0.f;
        for (int l = 0; l < NL; l++) sum += s_a[t][l];
        s_inv[t] = 1.f / (sum + 1.f);
    }
    __syncthreads();
    for (int i = t; i < NS * NL; i += 256) {
        int s = i >> 7;
        s_a[s][i & 127] *= s_inv[s];
    }
    __syncthreads();
    const float* encb = enc + (size_t)b * NL * NE2;
    #pragma unroll
    for (int eo = 0; eo < NE2 / 256; eo++) {
        int e = eo * 256 + t;
        float acc[NS];
        #pragma unroll
        for (int s = 0; s < NS; s++) acc[s] = 0.f;
        for (int l = 0; l < NL; l++) {
            float v = encb[l * NE2 + e];
            g_enc_bf[((size_t)b * NL + l) * NE2 + e] = __float2bfloat16(v);
            #pragma unroll
            for (int s = 0; s < NS; s++) acc[s] += s_a[s][l] * v;
        }
        #pragma unroll
        for (int s = 0; s < NS; s++)
            g_inps_bf[((size_t)b * NS + s) * NE2 + e] = __float2bfloat16(acc[s]);
    }
}

// ---------------- bf16 GEMM, 128x128 tile, cp.async double buffer ----------------
// C[m,n] = sum_k A[m,k] * W[n,k]; A,W bf16 row-major; C fp32. 256 threads.
__global__ __launch_bounds__(256) void gemm_bf16(
    const __nv_bfloat16* __restrict__ A, int lda,
    const __nv_bfloat16* __restrict__ W, int ldw,
    float* __restrict__ C, int ldc, int K) {
    __shared__ __align__(16) __nv_bfloat16 As[2][128][40];
    __shared__ __align__(16) __nv_bfloat16 Ws[2][128][40];

    const int tid  = threadIdx.x;
    const int warp = tid >> 5;
    const int wm   = warp & 1;
    const int wn   = warp >> 1;
    const int m0   = blockIdx.y * 128;
    const int n0   = blockIdx.x * 128;
    const int nkt  = K >> 5;

    wmma::fragment<wmma::accumulator, 16, 16, 16, float> acc[4][2];
    #pragma unroll
    for (int i = 0; i < 4; i++)
        #pragma unroll
        for (int j = 0; j < 2; j++) wmma::fill_fragment(acc[i][j], 0.f);

    auto issue = [&](int kt, int st) {
        int k0 = kt << 5;
        #pragma unroll
        for (int q = 0; q < 2; q++) {
            int chunk = tid * 2 + q;          // 0..511
            int r  = chunk >> 2;              // 0..127
            int c8 = (chunk & 3) * 8;
            cp16(&As[st][r][c8], A + (size_t)(m0 + r) * lda + k0 + c8);
            cp16(&Ws[st][r][c8], W + (size_t)(n0 + r) * ldw + k0 + c8);
        }
        CP_COMMIT();
    };

    issue(0, 0);
    for (int kt = 0; kt < nkt; kt++) {
        int st = kt & 1;
        if (kt + 1 < nkt) { issue(kt + 1, st ^ 1); CP_WAIT1(); }
        else             { CP_WAIT0(); }
        __syncthreads();
        #pragma unroll
        for (int kk = 0; kk < 32; kk += 16) {
            wmma::fragment<wmma::matrix_a, 16, 16, 16, __nv_bfloat16, wmma::row_major> af[4];
            wmma::fragment<wmma::matrix_b, 16, 16, 16, __nv_bfloat16, wmma::col_major> bf[2];
            #pragma unroll
            for (int i = 0; i < 4; i++)
                wmma::load_matrix_sync(af[i], &As[st][wm * 64 + i * 16][kk], 40);
            #pragma unroll
            for (int j = 0; j < 2; j++)
                wmma::load_matrix_sync(bf[j], &Ws[st][wn * 32 + j * 16][kk], 40);
            #pragma unroll
            for (int i = 0; i < 4; i++)
                #pragma unroll
                for (int j = 0; j < 2; j++)
                    wmma::mma_sync(acc[i][j], af[i], bf[j], acc[i][j]);
        }
        __syncthreads();
    }
    #pragma unroll
    for (int i = 0; i < 4; i++)
        #pragma unroll
        for (int j = 0; j < 2; j++)
            wmma::store_matrix_sync(
                C + (size_t)(m0 + wm * 64 + i * 16) * ldc + n0 + wn * 32 + j * 16,
                acc[i][j], ldc, wmma::mem_row_major);
}

// ---------------- bf16 GEMM, 64x64 tile (for h0: more CTAs) ----------------
__global__ __launch_bounds__(128) void gemm64_bf16(
    const __nv_bfloat16* __restrict__ A, int lda,
    const __nv_bfloat16* __restrict__ W, int ldw,
    float* __restrict__ C, int ldc, int K) {
    __shared__ __align__(16) __nv_bfloat16 As[2][64][40];
    __shared__ __align__(16) __nv_bfloat16 Ws[2][64][40];

    const int tid  = threadIdx.x;
    const int warp = tid >> 5;
    const int wm   = warp & 1;
    const int wn   = warp >> 1;
    const int m0   = blockIdx.y * 64;
    const int n0   = blockIdx.x * 64;
    const int nkt  = K >> 5;

    wmma::fragment<wmma::accumulator, 16, 16, 16, float> acc[2][2];
    #pragma unroll
    for (int i = 0; i < 2; i++)
        #pragma unroll
        for (int j = 0; j < 2; j++) wmma::fill_fragment(acc[i][j], 0.f);

    auto issue = [&](int kt, int st) {
        int k0 = kt << 5;
        #pragma unroll
        for (int q = 0; q < 2; q++) {
            int chunk = tid * 2 + q;          // 0..255
            int r  = chunk >> 2;              // 0..63
            int c8 = (chunk & 3) * 8;
            cp16(&As[st][r][c8], A + (size_t)(m0 + r) * lda + k0 + c8);
            cp16(&Ws[st][r][c8], W + (size_t)(n0 + r) * ldw + k0 + c8);
        }
        CP_COMMIT();
    };

    issue(0, 0);
    for (int kt = 0; kt < nkt; kt++) {
        int st = kt & 1;
        if (kt + 1 < nkt) { issue(kt + 1, st ^ 1); CP_WAIT1(); }
        else             { CP_WAIT0(); }
        __syncthreads();
        #pragma unroll
        for (int kk = 0; kk < 32; kk += 16) {
            wmma::fragment<wmma::matrix_a, 16, 16, 16, __nv_bfloat16, wmma::row_major> af[2];
            wmma::fragment<wmma::matrix_b, 16, 16, 16, __nv_bfloat16, wmma::col_major> bf[2];
            #pragma unroll
            for (int i = 0; i < 2; i++)
                wmma::load_matrix_sync(af[i], &As[st][wm * 32 + i * 16][kk], 40);
            #pragma unroll
            for (int j = 0; j < 2; j++)
                wmma::load_matrix_sync(bf[j], &Ws[st][wn * 32 + j * 16][kk], 40);
            #pragma unroll
            for (int i = 0; i < 2; i++)
                #pragma unroll
                for (int j = 0; j < 2; j++)
                    wmma::mma_sync(acc[i][j], af[i], bf[j], acc[i][j]);
        }
        __syncthreads();
    }
    #pragma unroll
    for (int i = 0; i < 2; i++)
        #pragma unroll
        for (int j = 0; j < 2; j++)
            wmma::store_matrix_sync(
                C + (size_t)(m0 + wm * 32 + i * 16) * ldc + n0 + wn * 32 + j * 16,
                acc[i][j], ldc, wmma::mem_row_major);
}

// ---------------- grid-wide software barrier (all GNC CTAs resident) ----------------
__device__ __forceinline__ void gridsync() {
    __syncthreads();
    if (threadIdx.x == 0) {
        unsigned gen;
        asm volatile("ld.acquire.gpu.u32 %0, [%1];" : "=r"(gen) : "l"(&g_bar_gen) : "memory");
        __threadfence();
        unsigned old = atomicAdd(&g_bar_arrive, 1u);
        if (old == GNC - 1) {
            g_bar_arrive = 0;
            __threadfence();
            atomicAdd(&g_bar_gen, 1u);
        } else {
            unsigned cur;
            do {
                __nanosleep(64);
                asm volatile("ld.acquire.gpu.u32 %0, [%1];" : "=r"(cur) : "l"(&g_bar_gen) : "memory");
            } while (cur == gen);
        }
    }
    __syncthreads();
}

// ---------------- persistent GRU: whole 12-step scan in one kernel ----------------
// grid = 64 CTAs: (colslice 0..15) x (batchgroup 0..3). Each CTA owns 32 batches x 32 h-cols.
// W_hh slice (96x512) held in smem across all steps. One gridsync per step.
__global__ __launch_bounds__(256) void k_gru_persist(
    const float* __restrict__ Whh, const float* __restrict__ bih,
    const float* __restrict__ bhh, const float* __restrict__ binit) {
    extern __shared__ __align__(16) char dyn[];
    __nv_bfloat16* sW  = (__nv_bfloat16*)dyn;          // [96][520]
    __nv_bfloat16* sH  = sW + 96 * 520;                // [32][520]
    float*         sGH = (float*)(sH + 32 * 520);      // [32][100]
    float*         sB  = sGH + 32 * 100;               // [192]: bih slice | bhh slice

    const int tid  = threadIdx.x;
    const int warp = tid >> 5;
    const int cs   = blockIdx.x & 15;
    const int bg   = blockIdx.x >> 4;
    const int C0   = cs * 32;
    const int B0   = bg * 32;

    // load W_hh slice rows {C0..C0+32, NH+C0.., 2NH+C0..} -> bf16 smem (once)
    for (int i = tid; i < 96 * 128; i += 256) {
        int r = i >> 7, c4 = (i & 127) * 4;
        int p = r >> 5, j = r & 31;
        float4 v = *(const float4*)(Whh + (size_t)(p * NH + C0 + j) * NH + c4);
        __nv_bfloat16* d = sW + r * 520 + c4;
        d[0] = __float2bfloat16(v.x); d[1] = __float2bfloat16(v.y);
        d[2] = __float2bfloat16(v.z); d[3] = __float2bfloat16(v.w);
    }
    if (tid < 96) {
        int p = tid >> 5, j = tid & 31;
        sB[tid]      = bih[p * NH + C0 + j];
        sB[96 + tid] = bhh[p * NH + C0 + j];
    }
    // h0: add b_init to our block of g_h; publish fp32 + bf16
    for (int i = tid; i < 32 * 32; i += 256) {
        int bi = i >> 5, ci = i & 31;
        int b = B0 + bi, c = C0 + ci;
        float v = g_h[b * NH + c] + binit[c];
        g_h[b * NH + c]  = v;
        g_hb[b * NH + c] = __float2bfloat16(v);
    }
    const int smax = g_gc[B0];  // gc sorted descending -> max over this batch block
    gridsync();

    for (int s = 0; s < NS; s++) {
        if (s < smax) {
            // load full h (bf16) for our 32 batches
            for (int i = tid; i < 32 * 64; i += 256) {
                int r = i >> 6, c8 = (i & 63) * 8;
                *(uint4*)(sH + r * 520 + c8) =
                    *(const uint4*)(g_hb + (size_t)(B0 + r) * NH + c8);
            }
            __syncthreads();
            // gh(32x96) = h(32x512) @ Wslice^T : warps 0..5, warp tile 32x16
            if (warp < 6) {
                wmma::fragment<wmma::accumulator, 16, 16, 16, float> acc[2];
                wmma::fill_fragment(acc[0], 0.f);
                wmma::fill_fragment(acc[1], 0.f);
                for (int kk = 0; kk < 512; kk += 16) {
                    wmma::fragment<wmma::matrix_a, 16, 16, 16, __nv_bfloat16, wmma::row_major> af[2];
                    wmma::fragment<wmma::matrix_b, 16, 16, 16, __nv_bfloat16, wmma::col_major> bf;
                    wmma::load_matrix_sync(af[0], sH + kk, 520);
                    wmma::load_matrix_sync(af[1], sH + 16 * 520 + kk, 520);
                    wmma::load_matrix_sync(bf, sW + warp * 16 * 520 + kk, 520);
                    wmma::mma_sync(acc[0], af[0], bf, acc[0]);
                    wmma::mma_sync(acc[1], af[1], bf, acc[1]);
                }
                wmma::store_matrix_sync(sGH + warp * 16, acc[0], 100, wmma::mem_row_major);
                wmma::store_matrix_sync(sGH + 16 * 100 + warp * 16, acc[1], 100, wmma::mem_row_major);
            }
            __syncthreads();
            // gate combine for our 32x32 block
            for (int i = tid; i < 32 * 32; i += 256) {
                int bi = i >> 5, ci = i & 31;
                int b = B0 + bi, c = C0 + ci;
                const float* x = g_xproj + ((size_t)b * NS + s) * NH3;
                float r = sigmoidf(x[c]           + sB[ci]      + sGH[bi * 100 + ci]      + sB[96 + ci]);
                float z = sigmoidf(x[NH + c]      + sB[32 + ci] + sGH[bi * 100 + 32 + ci] + sB[96 + 32 + ci]);
                float n = tanhf(x[2 * NH + c] + sB[64 + ci] +
                                r * (sGH[bi * 100 + 64 + ci] + sB[96 + 64 + ci]));
                float hp = g_h[b * NH + c];
                float hn = (1.f - z) * n + z * hp;
                g_h[b * NH + c]  = hn;
                g_hb[b * NH + c] = __float2bfloat16(hn);
                size_t oi = ((size_t)b * NS + s) * NH + c;
                g_outh[oi]    = hn;
                g_outh_bf[oi] = __float2bfloat16(hn);
            }
        }
        gridsync();
    }
}

// ---------------- fused plan logits + BCE ----------------
__global__ void k_plan(const int* __restrict__ segments,
                       const float* __restrict__ b_p1,
                       const float* __restrict__ W_p2,
                       const float* __restrict__ b_p2) {
    __shared__ float s_h[NS][NE];
    __shared__ float s_w2[NE];
    __shared__ float s_b1[NE];
    __shared__ float s_warp[8];
    int t = threadIdx.x;
    int b = blockIdx.y, ltile = blockIdx.x;  // (16, B)
    for (int i = t; i < NS * NE; i += 256) s_h[i >> 9][i & 511] = g_hpart[(size_t)b * NS * NE + i];
    for (int i = t; i < NE; i += 256) { s_w2[i] = W_p2[i]; s_b1[i] = b_p1[i]; }
    __syncthreads();

    int warp = t >> 5, lane = t & 31;
    int l = ltile * 8 + warp;
    const float* ep = g_epart + (size_t)(b * NL + l) * NE;
    float epr[16];
    #pragma unroll
    for (int j = 0; j < 16; j++) {
        int e = lane + 32 * j;
        epr[j] = ep[e] + s_b1[e];
    }

    int gcb = g_gc[b];
    int p   = g_idx[b];
    float bp2 = b_p2[0];
    float local = 0.f;
    for (int s = 0; s < gcb; s++) {
        float acc = 0.f;
        #pragma unroll
        for (int j = 0; j < 16; j++) {
            int e = lane + 32 * j;
            acc += fast_tanh(s_h[s][e] + epr[j]) * s_w2[e];
        }
        #pragma unroll
        for (int off = 16; off; off >>= 1) acc += __shfl_xor_sync(0xffffffffu, acc, off);
        if (lane == 0) {
            float pl  = acc + bp2;
            float tgt = (float)segments[(p * NS + s) * NL + l];
            local += softplusf(pl) - pl * tgt;
        }
    }
    if (lane == 0) s_warp[warp] = local;
    __syncthreads();
    if (t == 0) {
        float sum = 0.f;
        #pragma unroll
        for (int w = 0; w < 8; w++) sum += s_warp[w];
        g_plan_partial[b * 16 + ltile] = sum;
    }
}

// ---------------- stop loss + final reduction ----------------
__global__ void k_final(const float* __restrict__ W_stop,
                        const float* __restrict__ b_stop,
                        float* __restrict__ out) {
    __shared__ float s_w[NH];
    __shared__ float s_stop[32];
    __shared__ float s_red[1024];
    int t = threadIdx.x;  // 1024
    for (int i = t; i < NH; i += 1024) s_w[i] = W_stop[i];
    __syncthreads();

    int warp = t >> 5, lane = t & 31;
    float stop_local = 0.f;
    for (int bs = warp; bs < NB * NS; bs += 32) {
        int b = bs / NS, s = bs % NS;
        int gcb = g_gc[b];
        if (s < gcb) {
            const float* o = g_outh + (size_t)bs * NH;
            float a = 0.f;
            #pragma unroll
            for (int j = 0; j < 16; j++) a += o[lane + 32 * j] * s_w[lane + 32 * j];
            #pragma unroll
            for (int off = 16; off; off >>= 1) a += __shfl_xor_sync(0xffffffffu, a, off);
            if (lane == 0) {
                float logit = a + b_stop[0];
                float label = (s == gcb - 1) ? 1.f : 0.f;
                stop_local += softplusf(logit) - logit * label;
            }
        }
    }
    if (lane == 0) s_stop[warp] = stop_local;

    s_red[t] = g_plan_partial[t] + g_plan_partial[t + 1024];
    __syncthreads();
    for (int off = 512; off; off >>= 1) {
        if (t < off) s_red[t] += s_red[t + off];
        __syncthreads();
    }
    if (t == 0) {
        float stop_sum = 0.f;
        #pragma unroll
        for (int w = 0; w < 32; w++) stop_sum += s_stop[w];
        float ms = g_mask_sum;
        out[0] = stop_sum / ms;
        out[1] = s_red[0] / (ms * (float)NL);
    }
}

// ---------------- launch ----------------
extern "C" void kernel_launch(void* const* d_in, const int* in_sizes, int n_in,
                              void* d_out, int out_size) {
    const float* enc    = (const float*)d_in[0];
    const int*   segs   = (const int*)d_in[1];
    const int*   gcnt   = (const int*)d_in[2];
    const float* ginit  = (const float*)d_in[3];
    const float* W_init = (const float*)d_in[4];
    const float* b_init = (const float*)d_in[5];
    const float* W_ih   = (const float*)d_in[6];
    const float* b_ih   = (const float*)d_in[7];
    const float* W_hh   = (const float*)d_in[8];
    const float* b_hh   = (const float*)d_in[9];
    const float* W_p1   = (const float*)d_in[10];
    const float* b_p1   = (const float*)d_in[11];
    const float* W_p2   = (const float*)d_in[12];
    const float* b_p2   = (const float*)d_in[13];
    const float* W_stop = (const float*)d_in[14];
    const float* b_stop = (const float*)d_in[15];
    float* out = (float*)d_out;

    float *p_h, *p_xproj, *p_hpart, *p_epart;
    __nv_bfloat16 *p_inps_bf, *p_outh_bf, *p_enc_bf, *p_wp1_bf, *p_wih_bf, *p_ginit_bf, *p_winit_bf;
    cudaGetSymbolAddress((void**)&p_h,        g_h);
    cudaGetSymbolAddress((void**)&p_xproj,    g_xproj);
    cudaGetSymbolAddress((void**)&p_hpart,    g_hpart);
    cudaGetSymbolAddress((void**)&p_epart,    g_epart);
    cudaGetSymbolAddress((void**)&p_inps_bf,  g_inps_bf);
    cudaGetSymbolAddress((void**)&p_outh_bf,  g_outh_bf);
    cudaGetSymbolAddress((void**)&p_enc_bf,   g_enc_bf);
    cudaGetSymbolAddress((void**)&p_wp1_bf,   g_wp1_bf);
    cudaGetSymbolAddress((void**)&p_wih_bf,   g_wih_bf);
    cudaGetSymbolAddress((void**)&p_ginit_bf, g_ginit_bf);
    cudaGetSymbolAddress((void**)&p_winit_bf, g_winit_bf);

    static int smem_set = 0;
    if (!smem_set) {
        cudaFuncSetAttribute(k_gru_persist, cudaFuncAttributeMaxDynamicSharedMemorySize, 147456);
        smem_set = 1;
    }

    // weight converts (independent)
    k_cvt<<<(NE * NH3 / 4 + 255) / 256, 256>>>((const float4*)W_p1, (__nv_bfloat162*)p_wp1_bf, NE * NH3 / 4);
    k_cvt<<<(NH3 * NE2 / 4 + 255) / 256, 256>>>((const float4*)W_ih, (__nv_bfloat162*)p_wih_bf, NH3 * NE2 / 4);
    k_cvt<<<(NB * NKIN / 4 + 255) / 256, 256>>>((const float4*)ginit, (__nv_bfloat162*)p_ginit_bf, NB * NKIN / 4);
    k_cvt<<<(NH * NKIN / 4 + 255) / 256, 256>>>((const float4*)W_init, (__nv_bfloat162*)p_winit_bf, NH * NKIN / 4);

    k_sort<<<1, NB>>>(gcnt);
    k_inps<<<NB, 256>>>(enc, segs);   // -> g_inps_bf, g_enc_bf

    // epart = enc @ W1e^T  (16384 x 512, K=1024)
    gemm_bf16<<<dim3(NE / 128, (NB * NL) / 128), 256>>>(p_enc_bf, NE2, p_wp1_bf + NH, NH3, p_epart, NE, NE2);

    // h0 = ginit @ W_init^T  (128 x 512, K=2304); bias folded into persistent GRU
    gemm64_bf16<<<dim3(NH / 64, NB / 64), 128>>>(p_ginit_bf, NKIN, p_winit_bf, NKIN, p_h, NH, NKIN);

    // x_proj = inps @ W_ih^T  (1536 x 1536, K=1024)
    gemm_bf16<<<dim3(NH3 / 128, (NB * NS) / 128), 256>>>(p_inps_bf, NE2, p_wih_bf, NE2, p_xproj, NH3, NE2);

    // persistent GRU scan (h0 bias + 12 steps)
    k_gru_persist<<<GNC, 256, 147456>>>(W_hh, b_ih, b_hh, b_init);

    // hpart = outputs @ W1h^T  (1536 x 512, K=512)
    gemm_bf16<<<dim3(NE / 128, (NB * NS) / 128), 256>>>(p_outh_bf, NH, p_wp1_bf, NH3, p_hpart, NE, NH);

    k_plan<<<dim3(16, NB), 256>>>(segs, b_p1, W_p2, b_p2);
    k_final<<<1, 1024>>>(W_stop, b_stop, out);
}